// round 3
// baseline (speedup 1.0000x reference)
#include <cuda_runtime.h>
#include <cuda_bf16.h>

// Scratch for per-batch means of q,k,v: [batch][9] = (mq.xyz, mk.xyz, mv.xyz)
__device__ float g_means[16 * 9];

#define MAX_N 2048

// ---------------------------------------------------------------------------
// Kernel 1: per-batch means of q, k, v. One block per batch.
// ---------------------------------------------------------------------------
__global__ void vsa_means_kernel(const float* __restrict__ q,
                                 const float* __restrict__ k,
                                 const float* __restrict__ v,
                                 int N) {
    const int b = blockIdx.x;
    const float* qb = q + (size_t)b * N * 3;
    const float* kb = k + (size_t)b * N * 3;
    const float* vb = v + (size_t)b * N * 3;

    float s[9];
#pragma unroll
    for (int c = 0; c < 9; c++) s[c] = 0.0f;

    for (int i = threadIdx.x; i < N; i += blockDim.x) {
        const int o = i * 3;
        s[0] += qb[o + 0]; s[1] += qb[o + 1]; s[2] += qb[o + 2];
        s[3] += kb[o + 0]; s[4] += kb[o + 1]; s[5] += kb[o + 2];
        s[6] += vb[o + 0]; s[7] += vb[o + 1]; s[8] += vb[o + 2];
    }

    // warp reduce each accumulator
#pragma unroll
    for (int c = 0; c < 9; c++) {
#pragma unroll
        for (int off = 16; off > 0; off >>= 1)
            s[c] += __shfl_xor_sync(0xFFFFFFFFu, s[c], off);
    }

    __shared__ float red[8][9];
    const int warp = threadIdx.x >> 5;
    const int lane = threadIdx.x & 31;
    if (lane == 0) {
#pragma unroll
        for (int c = 0; c < 9; c++) red[warp][c] = s[c];
    }
    __syncthreads();

    const int nwarps = blockDim.x >> 5;
    if (threadIdx.x < 9) {
        float t = 0.0f;
        for (int w = 0; w < nwarps; w++) t += red[w][threadIdx.x];
        g_means[b * 9 + threadIdx.x] = t / (float)N;
    }
}

// ---------------------------------------------------------------------------
// Kernel 2: main. grid = (N/8, B), block = 256 threads (8 warps).
// Each warp owns one output row i; lanes stride over j.
//   u_i = cross(T_i, v_i) / (Z_i * N)
//   T_i = sum_j e_ij * C_ij,  Z_i = sum_j e_ij
//   C_ij = (q_i - mq) x (k_j - mk),  e_ij = exp(|C_ij| / sqrt(N))
// Centered k staged in SMEM as padded float4 for conflict-free LDS.128.
// ---------------------------------------------------------------------------
__global__ __launch_bounds__(256)
void vsa_main_kernel(const float* __restrict__ q,
                     const float* __restrict__ k,
                     const float* __restrict__ v,
                     float* __restrict__ out,
                     int N) {
    __shared__ float4 sk[MAX_N];

    const int b = blockIdx.y;
    const float* mp = &g_means[b * 9];
    const float mqx = mp[0], mqy = mp[1], mqz = mp[2];
    const float mkx = mp[3], mky = mp[4], mkz = mp[5];
    const float mvx = mp[6], mvy = mp[7], mvz = mp[8];

    // Stage centered k for this batch (coalesced global reads).
    const float* kb = k + (size_t)b * N * 3;
    for (int idx = threadIdx.x; idx < N * 3; idx += blockDim.x) {
        const int j = idx / 3;
        const int c = idx - 3 * j;
        const float m = (c == 0) ? mkx : ((c == 1) ? mky : mkz);
        ((float*)&sk[j])[c] = kb[idx] - m;
    }
    __syncthreads();

    const int warp = threadIdx.x >> 5;
    const int lane = threadIdx.x & 31;
    const int i = blockIdx.x * 8 + warp;

    const float* qi = q + ((size_t)b * N + i) * 3;
    const float qx = qi[0] - mqx;
    const float qy = qi[1] - mqy;
    const float qz = qi[2] - mqz;

    const float scale = rsqrtf((float)N);  // 1/sqrt(N)

    float sumE = 0.0f, Tx = 0.0f, Ty = 0.0f, Tz = 0.0f;

#pragma unroll 4
    for (int j = lane; j < N; j += 32) {
        const float4 kk = sk[j];
        // C = q_c x k_c
        const float Cx = fmaf(qy, kk.z, -qz * kk.y);
        const float Cy = fmaf(qz, kk.x, -qx * kk.z);
        const float Cz = fmaf(qx, kk.y, -qy * kk.x);
        const float n2 = fmaf(Cx, Cx, fmaf(Cy, Cy, Cz * Cz));
        // eta = |C| via n2 * rsqrt(n2); clamp avoids 0*inf -> NaN at n2 == 0.
        float r;
        asm("rsqrt.approx.f32 %0, %1;" : "=f"(r) : "f"(fmaxf(n2, 1e-30f)));
        const float eta = n2 * r;
        const float e = __expf(eta * scale);
        sumE += e;
        Tx = fmaf(e, Cx, Tx);
        Ty = fmaf(e, Cy, Ty);
        Tz = fmaf(e, Cz, Tz);
    }

    // warp reduction
#pragma unroll
    for (int off = 16; off > 0; off >>= 1) {
        sumE += __shfl_xor_sync(0xFFFFFFFFu, sumE, off);
        Tx   += __shfl_xor_sync(0xFFFFFFFFu, Tx,   off);
        Ty   += __shfl_xor_sync(0xFFFFFFFFu, Ty,   off);
        Tz   += __shfl_xor_sync(0xFFFFFFFFu, Tz,   off);
    }

    if (lane == 0) {
        const float* vi = v + ((size_t)b * N + i) * 3;
        const float vx = vi[0] - mvx;
        const float vy = vi[1] - mvy;
        const float vz = vi[2] - mvz;
        const float inv = 1.0f / (sumE * (float)N);
        float* o = out + ((size_t)b * N + i) * 3;
        o[0] = fmaf(Ty, vz, -Tz * vy) * inv;
        o[1] = fmaf(Tz, vx, -Tx * vz) * inv;
        o[2] = fmaf(Tx, vy, -Ty * vx) * inv;
    }
}

// ---------------------------------------------------------------------------
extern "C" void kernel_launch(void* const* d_in, const int* in_sizes, int n_in,
                              void* d_out, int out_size) {
    const float* q = (const float*)d_in[0];
    const float* k = (const float*)d_in[1];
    const float* v = (const float*)d_in[2];
    float* out = (float*)d_out;

    const int N = 2048;                 // fixed by problem spec
    const int B = out_size / (N * 3);   // = 4

    vsa_means_kernel<<<B, 256>>>(q, k, v, N);

    dim3 grid(N / 8, B);
    vsa_main_kernel<<<grid, 256>>>(q, k, v, out, N);
}

// round 4
// speedup vs baseline: 1.0570x; 1.0570x over previous
#include <cuda_runtime.h>
#include <cuda_bf16.h>

// Scratch for per-batch means of q,k,v: [batch][9] = (mq.xyz, mk.xyz, mv.xyz)
__device__ float g_means[16 * 9];

#define MAX_N 2048

// ---------------------------------------------------------------------------
// Kernel 1: per-batch means of q, k, v. One block per batch.
// ---------------------------------------------------------------------------
__global__ void vsa_means_kernel(const float* __restrict__ q,
                                 const float* __restrict__ k,
                                 const float* __restrict__ v,
                                 int N) {
    const int b = blockIdx.x;
    const float* qb = q + (size_t)b * N * 3;
    const float* kb = k + (size_t)b * N * 3;
    const float* vb = v + (size_t)b * N * 3;

    float s[9];
#pragma unroll
    for (int c = 0; c < 9; c++) s[c] = 0.0f;

    for (int i = threadIdx.x; i < N; i += blockDim.x) {
        const int o = i * 3;
        s[0] += qb[o + 0]; s[1] += qb[o + 1]; s[2] += qb[o + 2];
        s[3] += kb[o + 0]; s[4] += kb[o + 1]; s[5] += kb[o + 2];
        s[6] += vb[o + 0]; s[7] += vb[o + 1]; s[8] += vb[o + 2];
    }

#pragma unroll
    for (int c = 0; c < 9; c++) {
#pragma unroll
        for (int off = 16; off > 0; off >>= 1)
            s[c] += __shfl_xor_sync(0xFFFFFFFFu, s[c], off);
    }

    __shared__ float red[8][9];
    const int warp = threadIdx.x >> 5;
    const int lane = threadIdx.x & 31;
    if (lane == 0) {
#pragma unroll
        for (int c = 0; c < 9; c++) red[warp][c] = s[c];
    }
    __syncthreads();

    const int nwarps = blockDim.x >> 5;
    if (threadIdx.x < 9) {
        float t = 0.0f;
        for (int w = 0; w < nwarps; w++) t += red[w][threadIdx.x];
        g_means[b * 9 + threadIdx.x] = t / (float)N;
    }
}

// ---------------------------------------------------------------------------
// Kernel 2: main. grid = (N/8, B), block = 256 threads (8 warps).
// Warp owns output row i; lanes stride over j.
//   u_i = cross(T_i, v_i) / (Z_i * N)
//   T_i = sum_j e_ij * C_ij,  Z_i = sum_j e_ij
//   C_ij = (q_i - mq) x (k_j - mk),  e_ij = exp2(|C_ij| * log2e/sqrt(N))
//
// k tile staged packed float3 (24 KB): stride-3-bank LDS.32 is conflict-free,
// and 24 KB + <=36 regs (launch_bounds 256,7) gives 7 blocks/SM -> the whole
// 1024-block grid is ONE resident wave (7*148 = 1036 >= 1024). The previous
// 32 KB float4 tile capped residency at 6 blocks/SM -> 2 waves with a 136-
// block tail, which is where ~1/3 of the runtime went.
// ---------------------------------------------------------------------------
__global__ __launch_bounds__(256, 7)
void vsa_main_kernel(const float* __restrict__ q,
                     const float* __restrict__ k,
                     const float* __restrict__ v,
                     float* __restrict__ out,
                     int N) {
    __shared__ float sk[MAX_N * 3];  // packed [j].xyz, 24 KB

    const int b = blockIdx.y;
    const float* mp = &g_means[b * 9];
    const float mqx = mp[0], mqy = mp[1], mqz = mp[2];
    const float mkx = mp[3], mky = mp[4], mkz = mp[5];
    const float mvx = mp[6], mvy = mp[7], mvz = mp[8];

    // Stage centered k (coalesced reads, packed float3 store).
    const float* kb = k + (size_t)b * N * 3;
    for (int idx = threadIdx.x; idx < N * 3; idx += blockDim.x) {
        const int j = idx / 3;
        const int c = idx - 3 * j;
        const float m = (c == 0) ? mkx : ((c == 1) ? mky : mkz);
        sk[idx] = kb[idx] - m;
    }
    __syncthreads();

    const int warp = threadIdx.x >> 5;
    const int lane = threadIdx.x & 31;
    const int i = blockIdx.x * 8 + warp;

    const float* qi = q + ((size_t)b * N + i) * 3;
    const float qx = qi[0] - mqx;
    const float qy = qi[1] - mqy;
    const float qz = qi[2] - mqz;

    // combined constant: log2(e)/sqrt(N), so e_ij = ex2(n2 * c1 * rsqrt(n2))
    const float c1 = 1.4426950408889634f * rsqrtf((float)N);

    float sumE = 0.0f, Tx = 0.0f, Ty = 0.0f, Tz = 0.0f;

#pragma unroll 4
    for (int j = lane; j < N; j += 32) {
        const float kx = sk[j * 3 + 0];
        const float ky = sk[j * 3 + 1];
        const float kz = sk[j * 3 + 2];
        // C = q_c x k_c
        const float Cx = fmaf(qy, kz, -qz * ky);
        const float Cy = fmaf(qz, kx, -qx * kz);
        const float Cz = fmaf(qx, ky, -qy * kx);
        // epsilon folded into the FMA chain (replaces fmaxf): avoids 0*inf NaN
        const float n2 = fmaf(Cx, Cx, fmaf(Cy, Cy, fmaf(Cz, Cz, 1e-30f)));
        float r;
        asm("rsqrt.approx.f32 %0, %1;" : "=f"(r) : "f"(n2));
        const float t = n2 * c1;          // overlaps with rsqrt latency
        const float e = exp2f(t * r);     // single mul + EX2
        sumE += e;
        Tx = fmaf(e, Cx, Tx);
        Ty = fmaf(e, Cy, Ty);
        Tz = fmaf(e, Cz, Tz);
    }

    // warp reduction
#pragma unroll
    for (int off = 16; off > 0; off >>= 1) {
        sumE += __shfl_xor_sync(0xFFFFFFFFu, sumE, off);
        Tx   += __shfl_xor_sync(0xFFFFFFFFu, Tx,   off);
        Ty   += __shfl_xor_sync(0xFFFFFFFFu, Ty,   off);
        Tz   += __shfl_xor_sync(0xFFFFFFFFu, Tz,   off);
    }

    if (lane == 0) {
        const float* vi = v + ((size_t)b * N + i) * 3;
        const float vx = vi[0] - mvx;
        const float vy = vi[1] - mvy;
        const float vz = vi[2] - mvz;
        const float inv = 1.0f / (sumE * (float)N);
        float* o = out + ((size_t)b * N + i) * 3;
        o[0] = fmaf(Ty, vz, -Tz * vy) * inv;
        o[1] = fmaf(Tz, vx, -Tx * vz) * inv;
        o[2] = fmaf(Tx, vy, -Ty * vx) * inv;
    }
}

// ---------------------------------------------------------------------------
extern "C" void kernel_launch(void* const* d_in, const int* in_sizes, int n_in,
                              void* d_out, int out_size) {
    const float* q = (const float*)d_in[0];
    const float* k = (const float*)d_in[1];
    const float* v = (const float*)d_in[2];
    float* out = (float*)d_out;

    const int N = 2048;                 // fixed by problem spec
    const int B = out_size / (N * 3);   // = 4

    vsa_means_kernel<<<B, 256>>>(q, k, v, N);

    dim3 grid(N / 8, B);
    vsa_main_kernel<<<grid, 256>>>(q, k, v, out, N);
}

// round 5
// speedup vs baseline: 1.1393x; 1.0779x over previous
#include <cuda_runtime.h>
#include <cuda_bf16.h>

// Scratch for per-batch means of q,k,v: [batch][9] = (mq.xyz, mk.xyz, mv.xyz)
__device__ float g_means[16 * 9];

#define MAX_N 2048

// ---------------------------------------------------------------------------
// Kernel 1: per-batch means of q, k, v. One block per batch.
// ---------------------------------------------------------------------------
__global__ void vsa_means_kernel(const float* __restrict__ q,
                                 const float* __restrict__ k,
                                 const float* __restrict__ v,
                                 int N) {
    const int b = blockIdx.x;
    const float* qb = q + (size_t)b * N * 3;
    const float* kb = k + (size_t)b * N * 3;
    const float* vb = v + (size_t)b * N * 3;

    float s[9];
#pragma unroll
    for (int c = 0; c < 9; c++) s[c] = 0.0f;

    for (int i = threadIdx.x; i < N; i += blockDim.x) {
        const int o = i * 3;
        s[0] += qb[o + 0]; s[1] += qb[o + 1]; s[2] += qb[o + 2];
        s[3] += kb[o + 0]; s[4] += kb[o + 1]; s[5] += kb[o + 2];
        s[6] += vb[o + 0]; s[7] += vb[o + 1]; s[8] += vb[o + 2];
    }

#pragma unroll
    for (int c = 0; c < 9; c++) {
#pragma unroll
        for (int off = 16; off > 0; off >>= 1)
            s[c] += __shfl_xor_sync(0xFFFFFFFFu, s[c], off);
    }

    __shared__ float red[8][9];
    const int warp = threadIdx.x >> 5;
    const int lane = threadIdx.x & 31;
    if (lane == 0) {
#pragma unroll
        for (int c = 0; c < 9; c++) red[warp][c] = s[c];
    }
    __syncthreads();

    const int nwarps = blockDim.x >> 5;
    if (threadIdx.x < 9) {
        float t = 0.0f;
        for (int w = 0; w < nwarps; w++) t += red[w][threadIdx.x];
        g_means[b * 9 + threadIdx.x] = t / (float)N;
    }
}

// ---------------------------------------------------------------------------
// Kernel 2: main. grid = (N/8, B), block = 256 threads (8 warps).
// Warp owns output row i.  Lanes take 4 CONSECUTIVE j's per step
// (j = 4*lane + 128*step) so each lane's k-data is 12 contiguous floats
// = 3 x LDS.128 (bank-conflict-free: per 8-lane phase the 48-byte stride
// covers all 32 banks exactly once).
//
// k is staged PRE-SCALED: sk = (k - mk) * (log2e/sqrt(N)).  Then with
// C' = q_c x sk:   e_ij = exp2(|C'|) = ex2(sqrt(n2'))  -- no multiplies
// around the two MUFUs, no epsilon (sqrt.approx(0)=0 -> e=1).
// T' = sum e*C' = c1*T, fixed up once per row in the epilogue.
// ---------------------------------------------------------------------------
__global__ __launch_bounds__(256, 7)
void vsa_main_kernel(const float* __restrict__ q,
                     const float* __restrict__ k,
                     const float* __restrict__ v,
                     float* __restrict__ out,
                     int N) {
    __shared__ float4 sk4[MAX_N * 3 / 4];  // 1536 float4 = 24 KB

    const int b = blockIdx.y;
    const float* mp = &g_means[b * 9];
    const float mqx = mp[0], mqy = mp[1], mqz = mp[2];
    const float mkx = mp[3], mky = mp[4], mkz = mp[5];
    const float mvx = mp[6], mvy = mp[7], mvz = mp[8];

    const float c1 = 1.4426950408889634f * rsqrtf((float)N);  // log2e/sqrt(N)

    // Stage centered + pre-scaled k (coalesced global reads).
    {
        float* sk = (float*)sk4;
        const float* kb = k + (size_t)b * N * 3;
        for (int idx = threadIdx.x; idx < N * 3; idx += blockDim.x) {
            const int j = idx / 3;
            const int c = idx - 3 * j;
            const float m = (c == 0) ? mkx : ((c == 1) ? mky : mkz);
            sk[idx] = (kb[idx] - m) * c1;
        }
    }
    __syncthreads();

    const int warp = threadIdx.x >> 5;
    const int lane = threadIdx.x & 31;
    const int i = blockIdx.x * 8 + warp;

    const float* qi = q + ((size_t)b * N + i) * 3;
    const float qx = qi[0] - mqx;
    const float qy = qi[1] - mqy;
    const float qz = qi[2] - mqz;

    float sumE = 0.0f, Tx = 0.0f, Ty = 0.0f, Tz = 0.0f;

    // 4 j's per lane per step; 12 contiguous floats = 3 float4 loads.
    const float4* p = sk4 + 3 * lane;
    const int nsteps = N >> 7;  // N / 128

#define VSA_PAIR(KX, KY, KZ)                                        \
    {                                                               \
        const float Cx = fmaf(qy, (KZ), -qz * (KY));                \
        const float Cy = fmaf(qz, (KX), -qx * (KZ));                \
        const float Cz = fmaf(qx, (KY), -qy * (KX));                \
        const float n2 = fmaf(Cx, Cx, fmaf(Cy, Cy, Cz * Cz));       \
        float eta;                                                  \
        asm("sqrt.approx.f32 %0, %1;" : "=f"(eta) : "f"(n2));       \
        const float e = exp2f(eta);                                 \
        sumE += e;                                                  \
        Tx = fmaf(e, Cx, Tx);                                       \
        Ty = fmaf(e, Cy, Ty);                                       \
        Tz = fmaf(e, Cz, Tz);                                       \
    }

#pragma unroll 2
    for (int s = 0; s < nsteps; s++) {
        const float4 f0 = p[0];
        const float4 f1 = p[1];
        const float4 f2 = p[2];
        p += 96;  // 128 j's * 3 floats / 4 per float4
        VSA_PAIR(f0.x, f0.y, f0.z)
        VSA_PAIR(f0.w, f1.x, f1.y)
        VSA_PAIR(f1.z, f1.w, f2.x)
        VSA_PAIR(f2.y, f2.z, f2.w)
    }
#undef VSA_PAIR

    // warp reduction
#pragma unroll
    for (int off = 16; off > 0; off >>= 1) {
        sumE += __shfl_xor_sync(0xFFFFFFFFu, sumE, off);
        Tx   += __shfl_xor_sync(0xFFFFFFFFu, Tx,   off);
        Ty   += __shfl_xor_sync(0xFFFFFFFFu, Ty,   off);
        Tz   += __shfl_xor_sync(0xFFFFFFFFu, Tz,   off);
    }

    if (lane == 0) {
        const float* vi = v + ((size_t)b * N + i) * 3;
        const float vx = vi[0] - mvx;
        const float vy = vi[1] - mvy;
        const float vz = vi[2] - mvz;
        // T' = c1 * T  ->  divide by c1 here as well as by Z*N
        const float inv = 1.0f / (sumE * (float)N * c1);
        float* o = out + ((size_t)b * N + i) * 3;
        o[0] = fmaf(Ty, vz, -Tz * vy) * inv;
        o[1] = fmaf(Tz, vx, -Tx * vz) * inv;
        o[2] = fmaf(Tx, vy, -Ty * vx) * inv;
    }
}

// ---------------------------------------------------------------------------
extern "C" void kernel_launch(void* const* d_in, const int* in_sizes, int n_in,
                              void* d_out, int out_size) {
    const float* q = (const float*)d_in[0];
    const float* k = (const float*)d_in[1];
    const float* v = (const float*)d_in[2];
    float* out = (float*)d_out;

    const int N = 2048;                 // fixed by problem spec
    const int B = out_size / (N * 3);   // = 4

    vsa_means_kernel<<<B, 256>>>(q, k, v, N);

    dim3 grid(N / 8, B);
    vsa_main_kernel<<<grid, 256>>>(q, k, v, out, N);
}